// round 1
// baseline (speedup 1.0000x reference)
#include <cuda_runtime.h>
#include <cuda_bf16.h>
#include <stdint.h>

// ---------------- problem constants ----------------
#define NE    8
#define DIN   2048
#define DOUT  2048
#define NTOK  8192
#define NPAIR (NTOK * 2)

// ---------------- GEMM tiling ----------------
#define BM    128
#define BN    128
#define BK    32
#define ASTR  40              // padded smem row stride (elements); 80B -> conflict-free frag loads
#define MAXT  144             // worst-case M-tiles: 16384/128 + 8 = 136, padded
#define NSTEP (3 * (DIN / BK))  // 3 split passes x 64 k-steps

// ---------------- device scratch (no allocation allowed) ----------------
__device__ __align__(16) __nv_bfloat16 g_xhi[NTOK * DIN];
__device__ __align__(16) __nv_bfloat16 g_xlo[NTOK * DIN];
__device__ __align__(16) __nv_bfloat16 g_whi[NE * DOUT * DIN];
__device__ __align__(16) __nv_bfloat16 g_wlo[NE * DOUT * DIN];

__device__ int   g_cnt[NE];
__device__ int   g_pos[NE];
__device__ int   g_off[NE + 1];
__device__ int   g_tok[NPAIR];
__device__ float g_wt[NPAIR];
__device__ int   g_tile_e[MAXT];
__device__ int   g_tile_r0[MAXT];
__device__ int   g_tile_rows[MAXT];
__device__ int   g_ntiles;
__device__ int   g_topi[NPAIR];
__device__ float g_topp[NPAIR];

// ---------------- kernel 0: zero out + counters ----------------
__global__ void zero_kernel(float4* __restrict__ out4, int n4) {
    float4 z = make_float4(0.f, 0.f, 0.f, 0.f);
    for (int i = blockIdx.x * blockDim.x + threadIdx.x; i < n4;
         i += gridDim.x * blockDim.x)
        out4[i] = z;
    if (blockIdx.x == 0 && threadIdx.x < NE) {
        g_cnt[threadIdx.x] = 0;
        g_pos[threadIdx.x] = 0;
    }
}

// ---------------- kernel 1: gating (logits -> softmax -> top2) ----------------
__global__ void gate_kernel(const float* __restrict__ x,
                            const float* __restrict__ gw,
                            const float* __restrict__ gb) {
    int t = blockIdx.x;
    const float* xr = x + (size_t)t * DIN;
    float acc[NE];
#pragma unroll
    for (int e = 0; e < NE; e++) acc[e] = 0.f;

    for (int k = threadIdx.x; k < DIN; k += 256) {
        float xv = xr[k];
#pragma unroll
        for (int e = 0; e < NE; e++) acc[e] += xv * gw[e * DIN + k];
    }
#pragma unroll
    for (int off = 16; off > 0; off >>= 1)
#pragma unroll
        for (int e = 0; e < NE; e++)
            acc[e] += __shfl_xor_sync(0xffffffffu, acc[e], off);

    __shared__ float red[NE][8];
    int warp = threadIdx.x >> 5, lane = threadIdx.x & 31;
    if (lane == 0)
#pragma unroll
        for (int e = 0; e < NE; e++) red[e][warp] = acc[e];
    __syncthreads();

    if (threadIdx.x == 0) {
        float lg[NE];
#pragma unroll
        for (int e = 0; e < NE; e++) {
            float s = 0.f;
#pragma unroll
            for (int w = 0; w < 8; w++) s += red[e][w];
            lg[e] = s + gb[e];
        }
        float m = lg[0];
#pragma unroll
        for (int e = 1; e < NE; e++) m = fmaxf(m, lg[e]);
        float pz[NE];
        float Z = 0.f;
#pragma unroll
        for (int e = 0; e < NE; e++) { pz[e] = expf(lg[e] - m); Z += pz[e]; }

        int i1 = -1, i2 = -1;
        float m1 = -1.f, m2 = -1.f;
#pragma unroll
        for (int e = 0; e < NE; e++) {
            float p = pz[e];
            if (p > m1) { m2 = m1; i2 = i1; m1 = p; i1 = e; }
            else if (p > m2) { m2 = p; i2 = e; }
        }
        float inv = 1.f / Z;
        g_topi[t * 2]     = i1;  g_topp[t * 2]     = m1 * inv;
        g_topi[t * 2 + 1] = i2;  g_topp[t * 2 + 1] = m2 * inv;
        atomicAdd(&g_cnt[i1], 1);
        atomicAdd(&g_cnt[i2], 1);
    }
}

// ---------------- kernel 2: offsets + tile table (single thread; 8 experts) ----------------
__global__ void scan_kernel() {
    if (threadIdx.x != 0) return;
    int off = 0, nt = 0;
    for (int e = 0; e < NE; e++) {
        g_off[e] = off;
        int c = g_cnt[e];
        for (int r = 0; r < c; r += BM) {
            g_tile_e[nt] = e;
            g_tile_r0[nt] = off + r;
            g_tile_rows[nt] = (c - r < BM) ? (c - r) : BM;
            nt++;
        }
        off += c;
    }
    g_off[NE] = off;
    g_ntiles = nt;
}

// ---------------- kernel 3: scatter tokens into expert buckets ----------------
__global__ void scatter_kernel() {
    int t = blockIdx.x * blockDim.x + threadIdx.x;
    if (t >= NTOK) return;
#pragma unroll
    for (int k = 0; k < 2; k++) {
        int e = g_topi[t * 2 + k];
        float p = g_topp[t * 2 + k];
        int pos = atomicAdd(&g_pos[e], 1);
        int slot = g_off[e] + pos;
        g_tok[slot] = t;
        g_wt[slot] = p;
    }
}

// ---------------- kernels 4/5: fp32 -> bf16 hi/lo split ----------------
__global__ void split_x_kernel(const float2* __restrict__ src) {
    const int n2 = NTOK * DIN / 2;
    __nv_bfloat162* hi = (__nv_bfloat162*)g_xhi;
    __nv_bfloat162* lo = (__nv_bfloat162*)g_xlo;
    for (int i = blockIdx.x * blockDim.x + threadIdx.x; i < n2;
         i += gridDim.x * blockDim.x) {
        float2 f = src[i];
        __nv_bfloat16 hx = __float2bfloat16(f.x);
        __nv_bfloat16 hy = __float2bfloat16(f.y);
        __nv_bfloat162 h; h.x = hx; h.y = hy;
        __nv_bfloat162 l;
        l.x = __float2bfloat16(f.x - __bfloat162float(hx));
        l.y = __float2bfloat16(f.y - __bfloat162float(hy));
        hi[i] = h;
        lo[i] = l;
    }
}

__global__ void split_w_kernel(const float2* __restrict__ src) {
    const int n2 = NE * DOUT * DIN / 2;
    __nv_bfloat162* hi = (__nv_bfloat162*)g_whi;
    __nv_bfloat162* lo = (__nv_bfloat162*)g_wlo;
    for (int i = blockIdx.x * blockDim.x + threadIdx.x; i < n2;
         i += gridDim.x * blockDim.x) {
        float2 f = src[i];
        __nv_bfloat16 hx = __float2bfloat16(f.x);
        __nv_bfloat16 hy = __float2bfloat16(f.y);
        __nv_bfloat162 h; h.x = hx; h.y = hy;
        __nv_bfloat162 l;
        l.x = __float2bfloat16(f.x - __bfloat162float(hx));
        l.y = __float2bfloat16(f.y - __bfloat162float(hy));
        hi[i] = h;
        lo[i] = l;
    }
}

// ---------------- grouped GEMM (bf16 mma.sync, 3 split passes) ----------------
__device__ __forceinline__ void cpa16(uint32_t dst, const void* src) {
    asm volatile("cp.async.cg.shared.global [%0], [%1], 16;\n" :: "r"(dst), "l"(src));
}
__device__ __forceinline__ uint32_t lds32(const __nv_bfloat16* p) {
    return *(const uint32_t*)p;
}
__device__ __forceinline__ void mma16816(float* c, const uint32_t* a, const uint32_t* b) {
    asm volatile(
        "mma.sync.aligned.m16n8k16.row.col.f32.bf16.bf16.f32 "
        "{%0,%1,%2,%3}, {%4,%5,%6,%7}, {%8,%9}, {%0,%1,%2,%3};\n"
        : "+f"(c[0]), "+f"(c[1]), "+f"(c[2]), "+f"(c[3])
        : "r"(a[0]), "r"(a[1]), "r"(a[2]), "r"(a[3]), "r"(b[0]), "r"(b[1]));
}

__global__ __launch_bounds__(256, 2) void gemm_kernel(const float* __restrict__ bias,
                                                      float* __restrict__ out) {
    int mt = blockIdx.y;
    if (mt >= g_ntiles) return;
    int e    = g_tile_e[mt];
    int row0 = g_tile_r0[mt];
    int rows = g_tile_rows[mt];
    int n0   = blockIdx.x * BN;

    __shared__ __nv_bfloat16 As[2][BM * ASTR];
    __shared__ __nv_bfloat16 Bs[2][BM * ASTR];
    __shared__ int   tok_s[BM];
    __shared__ float wt_s[BM];

    int tid = threadIdx.x;
    if (tid < BM) {
        tok_s[tid] = (tid < rows) ? g_tok[row0 + tid] : 0;
        wt_s[tid]  = (tid < rows) ? g_wt[row0 + tid] : 0.f;
    }
    __syncthreads();

    int lrow = tid >> 1;
    int lcol = (tid & 1) << 4;  // 0 or 16
    size_t a_goff = (size_t)tok_s[lrow] * DIN + lcol;
    size_t b_goff = (size_t)(e * DOUT + n0 + lrow) * DIN + lcol;

    uint32_t aS0 = (uint32_t)__cvta_generic_to_shared(&As[0][lrow * ASTR + lcol]);
    uint32_t aS1 = (uint32_t)__cvta_generic_to_shared(&As[1][lrow * ASTR + lcol]);
    uint32_t bS0 = (uint32_t)__cvta_generic_to_shared(&Bs[0][lrow * ASTR + lcol]);
    uint32_t bS1 = (uint32_t)__cvta_generic_to_shared(&Bs[1][lrow * ASTR + lcol]);

    float acc[4][4][4];
#pragma unroll
    for (int im = 0; im < 4; im++)
#pragma unroll
        for (int in = 0; in < 4; in++)
#pragma unroll
            for (int j = 0; j < 4; j++) acc[im][in][j] = 0.f;

    int warp = tid >> 5, lane = tid & 31;
    int wm = warp >> 2, wn = warp & 3;   // 2 x 4 warp grid
    int g  = lane >> 2, tg = lane & 3;

    auto issue = [&](int step, int buf) {
        int p  = step >> 6;          // pass: 0 hi*hi, 1 hi*lo, 2 lo*hi
        int k0 = (step & 63) << 5;   // k offset
        const __nv_bfloat16* Ab = (p == 2) ? g_xlo : g_xhi;
        const __nv_bfloat16* Bb = (p == 1) ? g_wlo : g_whi;
        const __nv_bfloat16* as = Ab + a_goff + k0;
        const __nv_bfloat16* bs = Bb + b_goff + k0;
        uint32_t ad = buf ? aS1 : aS0;
        uint32_t bd = buf ? bS1 : bS0;
        cpa16(ad, as);       cpa16(ad + 16, as + 8);
        cpa16(bd, bs);       cpa16(bd + 16, bs + 8);
    };

    issue(0, 0);
    asm volatile("cp.async.commit_group;\n");
    int cur = 0;
    for (int s = 0; s < NSTEP; s++) {
        if (s + 1 < NSTEP) issue(s + 1, cur ^ 1);
        asm volatile("cp.async.commit_group;\n");
        asm volatile("cp.async.wait_group 1;\n");
        __syncthreads();

        const __nv_bfloat16* Ab = As[cur];
        const __nv_bfloat16* Bb = Bs[cur];
#pragma unroll
        for (int kk = 0; kk < BK; kk += 16) {
            uint32_t a[4][4], b[4][2];
#pragma unroll
            for (int im = 0; im < 4; im++) {
                const __nv_bfloat16* p0 = Ab + (wm * 64 + im * 16 + g) * ASTR + kk + tg * 2;
                a[im][0] = lds32(p0);
                a[im][1] = lds32(p0 + 8 * ASTR);
                a[im][2] = lds32(p0 + 8);
                a[im][3] = lds32(p0 + 8 * ASTR + 8);
            }
#pragma unroll
            for (int in = 0; in < 4; in++) {
                const __nv_bfloat16* p0 = Bb + (wn * 32 + in * 8 + g) * ASTR + kk + tg * 2;
                b[in][0] = lds32(p0);
                b[in][1] = lds32(p0 + 8);
            }
#pragma unroll
            for (int im = 0; im < 4; im++)
#pragma unroll
                for (int in = 0; in < 4; in++)
                    mma16816(acc[im][in], a[im], b[in]);
        }
        __syncthreads();
        cur ^= 1;
    }

    // epilogue: out[t, n] += p * (acc + bias)
#pragma unroll
    for (int im = 0; im < 4; im++) {
        int r = wm * 64 + im * 16 + g;
#pragma unroll
        for (int in = 0; in < 4; in++) {
            int c = n0 + wn * 32 + in * 8 + tg * 2;
            float b0 = bias[e * DOUT + c];
            float b1 = bias[e * DOUT + c + 1];
            if (r < rows) {
                int t = tok_s[r];
                float w = wt_s[r];
                atomicAdd(&out[(size_t)t * DOUT + c],     w * (acc[im][in][0] + b0));
                atomicAdd(&out[(size_t)t * DOUT + c + 1], w * (acc[im][in][1] + b1));
            }
            if (r + 8 < rows) {
                int t = tok_s[r + 8];
                float w = wt_s[r + 8];
                atomicAdd(&out[(size_t)t * DOUT + c],     w * (acc[im][in][2] + b0));
                atomicAdd(&out[(size_t)t * DOUT + c + 1], w * (acc[im][in][3] + b1));
            }
        }
    }
}

// ---------------- launch ----------------
extern "C" void kernel_launch(void* const* d_in, const int* in_sizes, int n_in,
                              void* d_out, int out_size) {
    const float* x  = (const float*)d_in[0];
    const float* ew = (const float*)d_in[1];
    const float* eb = (const float*)d_in[2];
    const float* gw = (const float*)d_in[3];
    const float* gb = (const float*)d_in[4];
    float* out = (float*)d_out;

    zero_kernel<<<4096, 256>>>((float4*)out, NTOK * DOUT / 4);
    gate_kernel<<<NTOK, 256>>>(x, gw, gb);
    scan_kernel<<<1, 32>>>();
    scatter_kernel<<<(NTOK + 255) / 256, 256>>>();
    split_x_kernel<<<4096, 256>>>((const float2*)x);
    split_w_kernel<<<8192, 256>>>((const float2*)ew);
    gemm_kernel<<<dim3(DOUT / BN, MAXT), 256>>>(eb, out);
}

// round 3
// speedup vs baseline: 2.5275x; 2.5275x over previous
#include <cuda_runtime.h>
#include <cuda_fp16.h>
#include <stdint.h>

// ---------------- problem constants ----------------
#define NE    8
#define DIN   2048
#define DOUT  2048
#define NTOK  8192
#define NPAIR (NTOK * 2)

// ---------------- GEMM tiling ----------------
#define BM     128
#define BN     128
#define BK     64
#define ASTR   72                  // padded smem row stride (halves); 144B rows -> conflict-free LDSM
#define KSTEPS (DIN / BK)          // 32
#define NTILE  (DOUT / BN)         // 16
#define MAXT   136                 // max M-tiles
#define MAXROWS (MAXT * BM)

#define STAGE_A_B  (BM * ASTR * 2)            // 18432 bytes per A stage
#define SMEM_WT    (4 * STAGE_A_B)            // offset of wt_s
#define SMEM_TOT   (SMEM_WT + BM * 4)

// ---------------- device scratch ----------------
__device__ __align__(16) __half g_xh[MAXROWS * DIN];     // gathered fp16 activations (expert-sorted)
__device__ __align__(16) __half g_wh[NE * DOUT * DIN];   // fp16 weights
__device__ __align__(16) float  g_pair[NPAIR * DOUT];    // per-(token,expert) weighted outputs

__device__ int   g_cnt[NE];
__device__ int   g_pos[NE];
__device__ int   g_off[NE + 1];
__device__ int   g_tok[NPAIR];
__device__ float g_wt[NPAIR];
__device__ int   g_slot[NPAIR];
__device__ int   g_topi[NPAIR];
__device__ float g_topp[NPAIR];
__device__ int   g_tile_e[MAXT];
__device__ int   g_tile_r0[MAXT];
__device__ int   g_tile_rows[MAXT];
__device__ int   g_ntiles;

// ---------------- helpers ----------------
__device__ __forceinline__ void cpa16(uint32_t dst, const void* src) {
    asm volatile("cp.async.cg.shared.global [%0], [%1], 16;\n" :: "r"(dst), "l"(src));
}
__device__ __forceinline__ void ldsm_x4(uint32_t* r, uint32_t addr) {
    asm volatile("ldmatrix.sync.aligned.m8n8.x4.shared.b16 {%0,%1,%2,%3}, [%4];"
                 : "=r"(r[0]), "=r"(r[1]), "=r"(r[2]), "=r"(r[3]) : "r"(addr));
}
__device__ __forceinline__ void mma16816(float* c, const uint32_t* a, const uint32_t* b) {
    asm volatile(
        "mma.sync.aligned.m16n8k16.row.col.f32.f16.f16.f32 "
        "{%0,%1,%2,%3}, {%4,%5,%6,%7}, {%8,%9}, {%0,%1,%2,%3};\n"
        : "+f"(c[0]), "+f"(c[1]), "+f"(c[2]), "+f"(c[3])
        : "r"(a[0]), "r"(a[1]), "r"(a[2]), "r"(a[3]), "r"(b[0]), "r"(b[1]));
}
__device__ __forceinline__ uint32_t pack2h(float a, float b) {
    __half2 h = __floats2half2_rn(a, b);
    return *(uint32_t*)&h;
}

// ---------------- kernel: reset counters ----------------
__global__ void reset_kernel() {
    if (threadIdx.x < NE) { g_cnt[threadIdx.x] = 0; g_pos[threadIdx.x] = 0; }
}

// ---------------- kernel: gating (fp32, matches reference ordering) ----------------
__global__ void gate_kernel(const float* __restrict__ x,
                            const float* __restrict__ gw,
                            const float* __restrict__ gb) {
    int t = blockIdx.x;
    const float* xr = x + (size_t)t * DIN;
    float acc[NE];
#pragma unroll
    for (int e = 0; e < NE; e++) acc[e] = 0.f;
    for (int k = threadIdx.x; k < DIN; k += 256) {
        float xv = xr[k];
#pragma unroll
        for (int e = 0; e < NE; e++) acc[e] += xv * gw[e * DIN + k];
    }
#pragma unroll
    for (int off = 16; off > 0; off >>= 1)
#pragma unroll
        for (int e = 0; e < NE; e++)
            acc[e] += __shfl_xor_sync(0xffffffffu, acc[e], off);

    __shared__ float red[NE][8];
    int warp = threadIdx.x >> 5, lane = threadIdx.x & 31;
    if (lane == 0)
#pragma unroll
        for (int e = 0; e < NE; e++) red[e][warp] = acc[e];
    __syncthreads();

    if (threadIdx.x == 0) {
        float lg[NE];
#pragma unroll
        for (int e = 0; e < NE; e++) {
            float s = 0.f;
#pragma unroll
            for (int w = 0; w < 8; w++) s += red[e][w];
            lg[e] = s + gb[e];
        }
        float m = lg[0];
#pragma unroll
        for (int e = 1; e < NE; e++) m = fmaxf(m, lg[e]);
        float pz[NE], Z = 0.f;
#pragma unroll
        for (int e = 0; e < NE; e++) { pz[e] = expf(lg[e] - m); Z += pz[e]; }
        int i1 = -1, i2 = -1; float m1 = -1.f, m2 = -1.f;
#pragma unroll
        for (int e = 0; e < NE; e++) {
            float p = pz[e];
            if (p > m1)      { m2 = m1; i2 = i1; m1 = p; i1 = e; }
            else if (p > m2) { m2 = p; i2 = e; }
        }
        float inv = 1.f / Z;
        g_topi[t * 2]     = i1;  g_topp[t * 2]     = m1 * inv;
        g_topi[t * 2 + 1] = i2;  g_topp[t * 2 + 1] = m2 * inv;
        atomicAdd(&g_cnt[i1], 1);
        atomicAdd(&g_cnt[i2], 1);
    }
}

// ---------------- kernel: scan + tile table ----------------
__global__ void scan_kernel() {
    if (threadIdx.x != 0) return;
    int off = 0, nt = 0;
    for (int e = 0; e < NE; e++) {
        g_off[e] = off;
        int c = g_cnt[e];
        for (int r = 0; r < c; r += BM) {
            g_tile_e[nt] = e;
            g_tile_r0[nt] = off + r;
            g_tile_rows[nt] = (c - r < BM) ? (c - r) : BM;
            nt++;
        }
        off += c;
    }
    g_off[NE] = off;
    g_ntiles = nt;
}

// ---------------- kernel: scatter ----------------
__global__ void scatter_kernel() {
    int t = blockIdx.x * blockDim.x + threadIdx.x;
    if (t >= NTOK) return;
#pragma unroll
    for (int k = 0; k < 2; k++) {
        int e = g_topi[t * 2 + k];
        float p = g_topp[t * 2 + k];
        int pos = atomicAdd(&g_pos[e], 1);
        int slot = g_off[e] + pos;
        g_tok[slot]       = t;
        g_wt[slot]        = p;
        g_slot[t * 2 + k] = slot;
    }
}

// ---------------- kernel: gather + fp32->fp16 of x (expert-sorted rows) ----------------
__global__ void gather_x_kernel(const float* __restrict__ x) {
    int slot = blockIdx.x;
    int t = g_tok[slot];
    const float4* xs = (const float4*)(x + (size_t)t * DIN);
    uint4* d = (uint4*)(g_xh + (size_t)slot * DIN);
    int i = threadIdx.x;                  // 256 threads, 8 elems each
    float4 a = xs[i * 2], b = xs[i * 2 + 1];
    uint4 o;
    o.x = pack2h(a.x, a.y);  o.y = pack2h(a.z, a.w);
    o.z = pack2h(b.x, b.y);  o.w = pack2h(b.z, b.w);
    d[i] = o;
}

// ---------------- kernel: fp32->fp16 of w ----------------
__global__ void convert_w_kernel(const float* __restrict__ w) {
    size_t idx = (size_t)blockIdx.x * 256 + threadIdx.x;   // 8 elems per thread
    const float4* ws = (const float4*)w;
    float4 a = ws[idx * 2], b = ws[idx * 2 + 1];
    uint4 o;
    o.x = pack2h(a.x, a.y);  o.y = pack2h(a.z, a.w);
    o.z = pack2h(b.x, b.y);  o.w = pack2h(b.z, b.w);
    ((uint4*)g_wh)[idx] = o;
}

// ---------------- grouped GEMM: fp16 mma.sync + ldmatrix, double-buffered ----------------
// dyn smem: As[2] @ 0, 18432 | Bs[2] @ 36864, 18432 | wt_s @ 73728
extern __shared__ char dsm[];

__global__ __launch_bounds__(256, 2) void gemm_kernel(const float* __restrict__ bias) {
    int mt = blockIdx.y;
    if (mt >= g_ntiles) return;
    int e    = g_tile_e[mt];
    int row0 = g_tile_r0[mt];
    int rows = g_tile_rows[mt];
    int n0   = blockIdx.x * BN;

    __half* As[2] = { (__half*)dsm, (__half*)(dsm + STAGE_A_B) };
    __half* Bs[2] = { (__half*)(dsm + 2 * STAGE_A_B), (__half*)(dsm + 3 * STAGE_A_B) };
    float* wt_s = (float*)(dsm + SMEM_WT);

    int tid = threadIdx.x;
    int wid = tid >> 5, lane = tid & 31;
    if (tid < BM) wt_s[tid] = (tid < rows) ? g_wt[row0 + tid] : 0.f;

    // ---- producer addressing: thread t loads row t>>1, 4 x 16B chunks ----
    int lrow = tid >> 1;
    int lch  = (tid & 1) * 4;                  // chunk base (each chunk = 8 halves)
    const __half* asrc = g_xh + (size_t)(row0 + lrow) * DIN + lch * 8;
    const __half* bsrc = g_wh + ((size_t)e * DOUT + n0 + lrow) * DIN + lch * 8;
    uint32_t aS[2], bS[2];
#pragma unroll
    for (int s = 0; s < 2; s++) {
        aS[s] = (uint32_t)__cvta_generic_to_shared(As[s] + lrow * ASTR + lch * 8);
        bS[s] = (uint32_t)__cvta_generic_to_shared(Bs[s] + lrow * ASTR + lch * 8);
    }

    auto issue = [&](int step, int buf) {
        const __half* as = asrc + step * BK;
        const __half* bs = bsrc + step * BK;
#pragma unroll
        for (int i = 0; i < 4; i++) {
            cpa16(aS[buf] + i * 16, as + i * 8);
            cpa16(bS[buf] + i * 16, bs + i * 8);
        }
    };

    // ---- compute addressing (ldmatrix) ----
    int wm = wid >> 2, wn = wid & 3;           // 2 x 4 warp grid; warp tile 64x32
    // A: lanes 0-15 -> row base+l, k+0 ; lanes 16-31 -> row base+(l-16), k+8
    int a_r = lane & 15, a_k = (lane >> 4) * 8;
    // B: m = lane>>3 : row = (m>>1)*8 + (lane&7), k = (m&1)*8
    int b_r = ((lane >> 4) * 8) + (lane & 7), b_k = ((lane >> 3) & 1) * 8;

    uint32_t aL[2][4], bL[2][2];
#pragma unroll
    for (int s = 0; s < 2; s++) {
#pragma unroll
        for (int im = 0; im < 4; im++)
            aL[s][im] = (uint32_t)__cvta_generic_to_shared(
                As[s] + (wm * 64 + im * 16 + a_r) * ASTR + a_k);
#pragma unroll
        for (int ip = 0; ip < 2; ip++)  // covers in = 2*ip, 2*ip+1
            bL[s][ip] = (uint32_t)__cvta_generic_to_shared(
                Bs[s] + (wn * 32 + ip * 16 + b_r) * ASTR + b_k);
    }

    float acc[4][4][4];
#pragma unroll
    for (int im = 0; im < 4; im++)
#pragma unroll
        for (int in = 0; in < 4; in++)
#pragma unroll
            for (int j = 0; j < 4; j++) acc[im][in][j] = 0.f;

    issue(0, 0);
    asm volatile("cp.async.commit_group;\n");
    int cur = 0;
    for (int s = 0; s < KSTEPS; s++) {
        if (s + 1 < KSTEPS) issue(s + 1, cur ^ 1);
        asm volatile("cp.async.commit_group;\n");
        asm volatile("cp.async.wait_group 1;\n");
        __syncthreads();

#pragma unroll
        for (int kk = 0; kk < BK; kk += 16) {
            uint32_t a[4][4], b[4][2];
#pragma unroll
            for (int im = 0; im < 4; im++)
                ldsm_x4(a[im], aL[cur][im] + kk * 2);
#pragma unroll
            for (int ip = 0; ip < 2; ip++) {
                uint32_t r[4];
                ldsm_x4(r, bL[cur][ip] + kk * 2);
                b[2 * ip][0] = r[0];     b[2 * ip][1] = r[1];
                b[2 * ip + 1][0] = r[2]; b[2 * ip + 1][1] = r[3];
            }
#pragma unroll
            for (int im = 0; im < 4; im++)
#pragma unroll
                for (int in = 0; in < 4; in++)
                    mma16816(acc[im][in], a[im], b[in]);
        }
        __syncthreads();
        cur ^= 1;
    }

    // ---- epilogue: weighted write to pair buffer (no atomics) ----
    int g = lane >> 2, tg = lane & 3;
#pragma unroll
    for (int im = 0; im < 4; im++) {
        int r0 = wm * 64 + im * 16 + g;
#pragma unroll
        for (int half = 0; half < 2; half++) {
            int r = r0 + half * 8;
            if (r < rows) {
                float w = wt_s[r];
                size_t ob = (size_t)(row0 + r) * DOUT + n0;
                const float* bp = bias + (size_t)e * DOUT + n0;
#pragma unroll
                for (int in = 0; in < 4; in++) {
                    int c = wn * 32 + in * 8 + tg * 2;
                    float2 v;
                    v.x = w * (acc[im][in][2 * half]     + bp[c]);
                    v.y = w * (acc[im][in][2 * half + 1] + bp[c + 1]);
                    *(float2*)(g_pair + ob + c) = v;
                }
            }
        }
    }
}

// ---------------- kernel: combine 2 slots per token ----------------
__global__ void combine_kernel(float* __restrict__ out) {
    int t = blockIdx.x;
    int s0 = g_slot[t * 2], s1 = g_slot[t * 2 + 1];
    const float4* p0 = (const float4*)(g_pair + (size_t)s0 * DOUT);
    const float4* p1 = (const float4*)(g_pair + (size_t)s1 * DOUT);
    float4* o = (float4*)(out + (size_t)t * DOUT);
#pragma unroll
    for (int k = 0; k < 2; k++) {
        int i = threadIdx.x + k * 256;
        float4 a = p0[i], b = p1[i];
        float4 v;
        v.x = a.x + b.x;  v.y = a.y + b.y;  v.z = a.z + b.z;  v.w = a.w + b.w;
        o[i] = v;
    }
}

// ---------------- launch ----------------
extern "C" void kernel_launch(void* const* d_in, const int* in_sizes, int n_in,
                              void* d_out, int out_size) {
    const float* x  = (const float*)d_in[0];
    const float* ew = (const float*)d_in[1];
    const float* eb = (const float*)d_in[2];
    const float* gw = (const float*)d_in[3];
    const float* gb = (const float*)d_in[4];
    float* out = (float*)d_out;

    cudaFuncSetAttribute(gemm_kernel, cudaFuncAttributeMaxDynamicSharedMemorySize, SMEM_TOT);

    reset_kernel<<<1, 32>>>();
    gate_kernel<<<NTOK, 256>>>(x, gw, gb);
    scan_kernel<<<1, 32>>>();
    scatter_kernel<<<(NTOK + 255) / 256, 256>>>();
    gather_x_kernel<<<NPAIR, 256>>>(x);
    convert_w_kernel<<<NE * DOUT * DIN / (256 * 8), 256>>>(ew);
    gemm_kernel<<<dim3(NTILE, MAXT), 256, SMEM_TOT>>>(eb);
    combine_kernel<<<NTOK, 256>>>(out);
}